// round 7
// baseline (speedup 1.0000x reference)
#include <cuda_runtime.h>

// Persistent single-kernel greedy transducer decode. B=32,T=1000,H=640,V=5000.
// Round 7: fused B->C2 (last-arriver), tree barrier, dynamic GEMM tickets. 2 barriers/step.

typedef unsigned long long ull;

constexpr int kB = 32;
constexpr int kT = 1000;
constexpr int kH = 640;
constexpr int kV = 5000;
constexpr int kG = 2560;

constexpr int NBLK = 592;
constexpr int NTHR = 256;

constexpr int HS = 8, DEP = 80;
constexpr int TILES_A = 320;    // 10 vch(512) x 8 hs x 4 bg(8b)
constexpr int TILES_CH = 160;   // 5 jch(512) x 8 hs x 4 bg
constexpr int POOL = TILES_A + TILES_CH;
constexpr int BCH = 8;          // 8 v-chunks x 32 b = 256 B-units
constexpr int PT = 3125;

// ---- device globals ----
__device__ __align__(16) float d_xwx[(size_t)kV * kH * 4];
__device__ __align__(16) float d_part[(size_t)HS * kB * kV];
__device__ __align__(16) float d_gpart[(size_t)HS * kB * kH * 4];
__device__ __align__(16) float d_jointT[kH * kB];
__device__ __align__(16) float d_hT[kH * kB];
__device__ __align__(16) float d_c[kB * kH];
__device__ float d_scores[kB];
__device__ int   d_tok[kB];
__device__ float d_bmax[kB * BCH];
__device__ int   d_bidx[kB * BCH];
__device__ float d_bsum[kB * BCH];
__device__ int   d_bcnt[kB];

// barrier state (replay-safe: self-resetting counters, monotonic gen)
__device__ __align__(128) unsigned g_leaf[8][32];
__device__ __align__(128) unsigned g_root[32];
__device__ __align__(128) unsigned g_gen[32];
__device__ __align__(128) unsigned g_tk[2][32];   // ping-pong GEMM tickets

__device__ __forceinline__ unsigned ld_cg(const unsigned* p) {
    unsigned v;
    asm volatile("ld.global.cg.u32 %0, [%1];" : "=r"(v) : "l"(p));
    return v;
}

__device__ __forceinline__ void grid_barrier() {
    __syncthreads();
    if (threadIdx.x == 0) {
        __threadfence();
        unsigned my = ld_cg(&g_gen[0]);
        unsigned* leaf = &g_leaf[blockIdx.x & 7][0];
        if (atomicAdd(leaf, 1u) == (unsigned)(NBLK / 8 - 1)) {
            atomicExch(leaf, 0u);
            __threadfence();
            if (atomicAdd(&g_root[0], 1u) == 7u) {
                atomicExch(&g_root[0], 0u);
                __threadfence();
                atomicAdd(&g_gen[0], 1u);
            } else {
                while (ld_cg(&g_gen[0]) == my) { __nanosleep(20); }
            }
        } else {
            while (ld_cg(&g_gen[0]) == my) { __nanosleep(30); }
        }
        __threadfence();
    }
    __syncthreads();
}

// ---- f32x2 helpers ----
__device__ __forceinline__ ull pack2(float w) {
    ull r; asm("mov.b64 %0, {%1, %1};" : "=l"(r) : "f"(w)); return r;
}
__device__ __forceinline__ void ffma2(ull& a, ull s, ull w) {
    asm("fma.rn.f32x2 %0, %1, %2, %0;" : "+l"(a) : "l"(s), "l"(w));
}
__device__ __forceinline__ float2 unpack2(ull a) {
    float2 f; asm("mov.b64 {%0, %1}, %2;" : "=f"(f.x), "=f"(f.y) : "l"(a)); return f;
}
__device__ __forceinline__ float sigf(float x) { return 1.f / (1.f + expf(-x)); }

// 2-column x 8-batch dot over 80 depth rows, 8-row weight prefetch ring.
__device__ __forceinline__ void dot80_2(ull a1[4], ull a2[4], const float (*sA)[8],
                                        const float* __restrict__ w1p,
                                        const float* __restrict__ w2p, size_t ws) {
    float b1[8], b2[8];
#pragma unroll
    for (int j = 0; j < 8; j++) { b1[j] = w1p[j * ws]; b2[j] = w2p[j * ws]; }
    const float* f1 = w1p + 8 * ws;
    const float* f2 = w2p + 8 * ws;
#pragma unroll
    for (int g = 0; g < DEP; ++g) {
        float c1 = b1[g & 7], c2 = b2[g & 7];
        if (g < DEP - 8) { b1[g & 7] = *f1; f1 += ws; b2[g & 7] = *f2; f2 += ws; }
        ull W1 = pack2(c1), W2 = pack2(c2);
        const double2* sp = reinterpret_cast<const double2*>(sA[g]);
        double2 q0 = sp[0], q1 = sp[1];
        ull s0 = __double_as_longlong(q0.x);
        ull s1 = __double_as_longlong(q0.y);
        ull s2 = __double_as_longlong(q1.x);
        ull s3 = __double_as_longlong(q1.y);
        ffma2(a1[0], s0, W1); ffma2(a1[1], s1, W1);
        ffma2(a1[2], s2, W1); ffma2(a1[3], s3, W1);
        ffma2(a2[0], s0, W2); ffma2(a2[1], s1, W2);
        ffma2(a2[2], s2, W2); ffma2(a2[3], s3, W2);
    }
}

__device__ __forceinline__ void fill_T8(float (*dst)[8], const float* __restrict__ srcT,
                                        int bg, int hbase) {
    for (int idx = threadIdx.x; idx < DEP * 8; idx += NTHR) {
        int hh = idx >> 3, bb = idx & 7;
        dst[hh][bb] = srcT[(hbase + hh) * kB + bg * 8 + bb];
    }
}

// ---- A tile: jointT @ Wc -> d_part ----
__device__ void A_tile(int tt, float (*sA)[8], const float* __restrict__ Wc) {
    int hs = tt & 7, vch = (tt >> 3) % 10, bg = tt / 80;
    int hbase = hs * DEP;
    fill_T8(sA, d_jointT, bg, hbase);
    __syncthreads();
    int tid = threadIdx.x;
    int v1 = vch * 512 + tid;
    int v2 = v1 + 256;
    bool ok2 = v2 < kV;
    const float* w1 = Wc + (size_t)hbase * kV + v1;
    const float* w2 = Wc + (size_t)hbase * kV + (ok2 ? v2 : v1);
    ull a1[4] = {0, 0, 0, 0}, a2[4] = {0, 0, 0, 0};
    dot80_2(a1, a2, sA, w1, w2, kV);
    size_t rb = (size_t)(hs * kB + bg * 8) * kV;
#pragma unroll
    for (int i = 0; i < 4; i++) {
        float2 f = unpack2(a1[i]);
        d_part[rb + (size_t)(2 * i) * kV + v1] = f.x;
        d_part[rb + (size_t)(2 * i + 1) * kV + v1] = f.y;
    }
    if (ok2) {
#pragma unroll
        for (int i = 0; i < 4; i++) {
            float2 f = unpack2(a2[i]);
            d_part[rb + (size_t)(2 * i) * kV + v2] = f.x;
            d_part[rb + (size_t)(2 * i + 1) * kV + v2] = f.y;
        }
    }
}

// ---- CH tile: hT @ Wh -> d_gpart ----
__device__ void CH_tile(int u, float (*sA)[8], const float* __restrict__ Wh) {
    int hs = u & 7, jch = (u >> 3) % 5, bg = u / 40;
    int hbase = hs * DEP;
    fill_T8(sA, d_hT, bg, hbase);
    __syncthreads();
    int tid = threadIdx.x;
    int j1 = jch * 512 + tid;
    int j2 = j1 + 256;
    const float* w1 = Wh + (size_t)hbase * kG + j1;
    const float* w2 = Wh + (size_t)hbase * kG + j2;
    ull a1[4] = {0, 0, 0, 0}, a2[4] = {0, 0, 0, 0};
    dot80_2(a1, a2, sA, w1, w2, kG);
    int g1 = j1 / kH, k1 = j1 - g1 * kH;
    int g2 = j2 / kH, k2 = j2 - g2 * kH;
#pragma unroll
    for (int i = 0; i < 4; i++) {
        float2 f = unpack2(a1[i]);
        d_gpart[(((size_t)hs * kB + bg * 8 + 2 * i) * kH + k1) * 4 + g1] = f.x;
        d_gpart[(((size_t)hs * kB + bg * 8 + 2 * i + 1) * kH + k1) * 4 + g1] = f.y;
    }
#pragma unroll
    for (int i = 0; i < 4; i++) {
        float2 f = unpack2(a2[i]);
        d_gpart[(((size_t)hs * kB + bg * 8 + 2 * i) * kH + k2) * 4 + g2] = f.x;
        d_gpart[(((size_t)hs * kB + bg * 8 + 2 * i + 1) * kH + k2) * 4 + g2] = f.y;
    }
}

// ---- fused phase B -> C2: partial reduce, last arriver runs LSTM+emit for its b ----
__device__ void phaseBC(int t, const float* __restrict__ bc, const float* __restrict__ tn,
                        const float* __restrict__ bias, float* __restrict__ out,
                        float* s_f, int* s_i, float* s_s, int* s_last) {
    int u = blockIdx.x;            // < kB*BCH = 256
    int b = u >> 3, ch = u & 7;
    int v0 = ch * 640;
    int tid = threadIdx.x;

    float m = -1e30f; int mi = 0x7fffffff; float se = 0.f;
    int v = v0 + 4 * tid;
    if (tid < 160 && v < kV) {
        float4 s = *(const float4*)&bc[v];
#pragma unroll
        for (int hs = 0; hs < HS; hs++) {
            float4 p = *(const float4*)&d_part[((size_t)(hs * kB + b)) * kV + v];
            s.x += p.x; s.y += p.y; s.z += p.z; s.w += p.w;
        }
        se = expf(s.x) + expf(s.y) + expf(s.z) + expf(s.w);
        m = s.x; mi = v;
        if (s.y > m) { m = s.y; mi = v + 1; }
        if (s.z > m) { m = s.z; mi = v + 2; }
        if (s.w > m) { m = s.w; mi = v + 3; }
    }
    s_f[tid] = m; s_i[tid] = mi; s_s[tid] = se;
    __syncthreads();
    for (int w = 128; w; w >>= 1) {
        if (tid < w) {
            float om = s_f[tid + w]; int oi = s_i[tid + w];
            if (om > s_f[tid] || (om == s_f[tid] && oi < s_i[tid])) { s_f[tid] = om; s_i[tid] = oi; }
            s_s[tid] += s_s[tid + w];
        }
        __syncthreads();
    }
    if (tid == 0) {
        d_bmax[u] = s_f[0]; d_bidx[u] = s_i[0]; d_bsum[u] = s_s[0];
        __threadfence();
        *s_last = (atomicAdd(&d_bcnt[b], 1) == BCH - 1) ? 1 : 0;
    }
    __syncthreads();
    if (!*s_last) return;

    // ---- this block is the last arriver for batch b: run C2 ----
    __threadfence();
    float M = -1e30f; int MI = 0; float S = 0.f;
#pragma unroll
    for (int c2 = 0; c2 < BCH; c2++) {
        float cm = __ldcg(&d_bmax[b * BCH + c2]);
        int ci = __ldcg(&d_bidx[b * BCH + c2]);
        S += __ldcg(&d_bsum[b * BCH + c2]);
        if (cm > M) { M = cm; MI = ci; }
    }
    int upd = (MI != 0);
    int nt = upd ? MI : __ldcg(&d_tok[b]);

    if (t < kT - 1) {
        for (int k = tid; k < kH; k += NTHR) {
            float hnew;
            if (upd) {
                float4 a = __ldcg((const float4*)&d_xwx[((size_t)nt * kH + k) * 4]);
                a.x += bias[k]; a.y += bias[kH + k];
                a.z += bias[2 * kH + k]; a.w += bias[3 * kH + k];
#pragma unroll
                for (int hs = 0; hs < HS; hs++) {
                    float4 p = __ldcg((const float4*)&d_gpart[(((size_t)hs * kB + b) * kH + k) * 4]);
                    a.x += p.x; a.y += p.y; a.z += p.z; a.w += p.w;
                }
                float cold = __ldcg(&d_c[b * kH + k]);
                float c2v = sigf(a.y) * cold + sigf(a.x) * tanhf(a.z);
                float h2 = sigf(a.w) * tanhf(c2v);
                d_c[b * kH + k] = c2v;
                d_hT[k * kB + b] = h2;
                hnew = h2;
            } else {
                hnew = __ldcg(&d_hT[k * kB + b]);
            }
            d_jointT[k * kB + b] = tanhf(tn[((size_t)b * kT + (t + 1)) * kH + k] + hnew);
        }
    }

    if (tid == 0) {
        float val = M - logf(S);
        float sc = __ldcg(&d_scores[b]) + (upd ? val : 0.f);
        d_scores[b] = sc;
        if (t == kT - 1) out[b] = sc;
        out[kB + (size_t)b * kT + t] = (float)(upd ? MI : 0);
        if (upd) d_tok[b] = MI;
        d_bcnt[b] = 0;                  // reset for next step
    }
}

// ---- one-time: xWx = embed @ Wx -> [v][k][gate] ----
__device__ void precompute_xwx(const float* __restrict__ embed, const float* __restrict__ Wx,
                               float (*sA)[8]) {
    for (int tp = blockIdx.x; tp < PT; tp += NBLK) {
        int rb = tp / 5, jch = tp % 5;
        int v0 = rb * 8;
        int tid = threadIdx.x;
        int j1 = jch * 512 + tid, j2 = j1 + 256;
        ull a1[4] = {0, 0, 0, 0}, a2[4] = {0, 0, 0, 0};
        for (int hs = 0; hs < HS; hs++) {
            __syncthreads();
            for (int idx = tid; idx < DEP * 8; idx += NTHR) {
                int hh = idx >> 3, bb = idx & 7;
                sA[hh][bb] = embed[(size_t)(v0 + bb) * kH + hs * DEP + hh];
            }
            __syncthreads();
            dot80_2(a1, a2, sA, Wx + (size_t)(hs * DEP) * kG + j1,
                    Wx + (size_t)(hs * DEP) * kG + j2, kG);
        }
        int g1 = j1 / kH, k1 = j1 - g1 * kH;
        int g2 = j2 / kH, k2 = j2 - g2 * kH;
#pragma unroll
        for (int i = 0; i < 4; i++) {
            float2 f1 = unpack2(a1[i]);
            float2 f2 = unpack2(a2[i]);
            d_xwx[((size_t)(v0 + 2 * i) * kH + k1) * 4 + g1] = f1.x;
            d_xwx[((size_t)(v0 + 2 * i + 1) * kH + k1) * 4 + g1] = f1.y;
            d_xwx[((size_t)(v0 + 2 * i) * kH + k2) * 4 + g2] = f2.x;
            d_xwx[((size_t)(v0 + 2 * i + 1) * kH + k2) * 4 + g2] = f2.y;
        }
        __syncthreads();
    }
}

__device__ void initC2(const float* __restrict__ tn, const float* __restrict__ bias) {
    int gid = blockIdx.x * NTHR + threadIdx.x;
    if (gid >= kB * kH) return;
    int b = gid / kH, k = gid - b * kH;
    float4 a = *(const float4*)&d_xwx[(size_t)k * 4];
    a.x += bias[k]; a.y += bias[kH + k]; a.z += bias[2 * kH + k]; a.w += bias[3 * kH + k];
    float c1 = sigf(a.x) * tanhf(a.z);
    float h1 = sigf(a.w) * tanhf(c1);
    d_c[gid] = c1;
    d_hT[k * kB + b] = h1;
    d_jointT[k * kB + b] = tanhf(tn[(size_t)b * kT * kH + k] + h1);
    if (k == 0) { d_scores[b] = 0.f; d_tok[b] = 0; d_bcnt[b] = 0; }
}

__global__ void __launch_bounds__(NTHR, 4)
transducer_kernel(const float* __restrict__ tn, const float* __restrict__ embed,
                  const float* __restrict__ Wx, const float* __restrict__ Wh,
                  const float* __restrict__ bias, const float* __restrict__ Wc,
                  const float* __restrict__ bc, float* __restrict__ out) {
    __shared__ __align__(16) float sA[DEP][8];
    __shared__ float s_f[NTHR];
    __shared__ int   s_i[NTHR];
    __shared__ float s_s[NTHR];
    __shared__ int   s_last;
    __shared__ int   s_tt;

    // per-replay init of tickets (barrier/leaf/root/gen are self-resetting)
    if (blockIdx.x == 0 && threadIdx.x == 0) {
        atomicExch(&g_tk[0][0], 0u);
        atomicExch(&g_tk[1][0], 0u);
    }
    precompute_xwx(embed, Wx, sA);
    grid_barrier();
    initC2(tn, bias);
    grid_barrier();

    for (int t = 0; t < kT; ++t) {
        // GEMM phase: dynamic tickets over A+CH tiles
        int pool = (t < kT - 1) ? POOL : TILES_A;
        for (;;) {
            if (threadIdx.x == 0) s_tt = (int)atomicAdd(&g_tk[t & 1][0], 1u);
            __syncthreads();
            int tt = s_tt;
            if (tt >= pool) break;
            if (tt < TILES_A) A_tile(tt, sA, Wc);
            else CH_tile(tt - TILES_A, sA, Wh);
            __syncthreads();
        }
        grid_barrier();

        // fused B -> C2 phase (blocks 0..255); block 300 resets this parity's ticket
        if (blockIdx.x < kB * BCH) {
            phaseBC(t, bc, tn, bias, out, s_f, s_i, s_s, &s_last);
        } else if (blockIdx.x == 300 && threadIdx.x == 0) {
            atomicExch(&g_tk[t & 1][0], 0u);
        }
        grid_barrier();
    }
}

extern "C" void kernel_launch(void* const* d_in, const int* in_sizes, int n_in,
                              void* d_out, int out_size) {
    const float* tn    = (const float*)d_in[0];
    const float* embed = (const float*)d_in[1];
    const float* Wx    = (const float*)d_in[2];
    const float* Wh    = (const float*)d_in[3];
    const float* bias  = (const float*)d_in[4];
    const float* Wc    = (const float*)d_in[5];
    const float* bc    = (const float*)d_in[6];
    float* out = (float*)d_out;
    (void)in_sizes; (void)n_in; (void)out_size;
    transducer_kernel<<<NBLK, NTHR>>>(tn, embed, Wx, Wh, bias, Wc, bc, out);
}

// round 8
// speedup vs baseline: 1.2588x; 1.2588x over previous
#include <cuda_runtime.h>

// Persistent single-kernel greedy transducer decode. B=32,T=1000,H=640,V=5000.
// Round 8: round-6 base + (A||CH in phase1) + fused B->cooperative C2. 2 barriers/step.

typedef unsigned long long ull;

constexpr int kB = 32;
constexpr int kT = 1000;
constexpr int kH = 640;
constexpr int kV = 5000;
constexpr int kG = 2560;

constexpr int NBLK = 592;
constexpr int NTHR = 256;

constexpr int HS = 8, DEP = 80;
constexpr int TILES_A = 320;    // 10 vch(512) x 8 hs x 4 bg(8b)
constexpr int TILES_CH = 160;   // 5 jch(512) x 8 hs x 4 bg
constexpr int BCH = 8;          // 8 v-chunks x 32 b = 256 B-units
constexpr int PT = 3125;

// ---- device globals ----
__device__ __align__(16) float d_xwx[(size_t)kV * kH * 4];
__device__ __align__(16) float d_part[(size_t)HS * kB * kV];
__device__ __align__(16) float d_gpart[(size_t)HS * kB * kH * 4];
__device__ __align__(16) float d_jointT[kH * kB];
__device__ __align__(16) float d_hT[kH * kB];
__device__ __align__(16) float d_c[kB * kH];
__device__ float d_scores[kB];
__device__ int   d_tok[kB];
__device__ float d_bmax[kB * BCH];
__device__ int   d_bidx[kB * BCH];
__device__ float d_bsum[kB * BCH];
__device__ int   d_bcnt[2][kB];        // ping-pong arrival counters per batch

__device__ __align__(128) unsigned g_count[32];
__device__ __align__(128) unsigned g_gen[32];

__device__ __forceinline__ unsigned ld_cg(const unsigned* p) {
    unsigned v;
    asm volatile("ld.global.cg.u32 %0, [%1];" : "=r"(v) : "l"(p));
    return v;
}
__device__ __forceinline__ int ld_cg_i(const int* p) {
    int v;
    asm volatile("ld.global.cg.s32 %0, [%1];" : "=r"(v) : "l"(p));
    return v;
}

__device__ __forceinline__ void grid_barrier() {
    __syncthreads();
    if (threadIdx.x == 0) {
        __threadfence();
        unsigned my = ld_cg(&g_gen[0]);
        if (atomicAdd(&g_count[0], 1u) == (unsigned)(NBLK - 1)) {
            atomicExch(&g_count[0], 0u);
            __threadfence();
            atomicAdd(&g_gen[0], 1u);
        } else {
            while (ld_cg(&g_gen[0]) == my) { __nanosleep(40); }
        }
        __threadfence();
    }
    __syncthreads();
}

// ---- f32x2 helpers ----
__device__ __forceinline__ ull pack2(float w) {
    ull r; asm("mov.b64 %0, {%1, %1};" : "=l"(r) : "f"(w)); return r;
}
__device__ __forceinline__ void ffma2(ull& a, ull s, ull w) {
    asm("fma.rn.f32x2 %0, %1, %2, %0;" : "+l"(a) : "l"(s), "l"(w));
}
__device__ __forceinline__ float2 unpack2(ull a) {
    float2 f; asm("mov.b64 {%0, %1}, %2;" : "=f"(f.x), "=f"(f.y) : "l"(a)); return f;
}
__device__ __forceinline__ float sigf(float x) { return 1.f / (1.f + expf(-x)); }

// 2-column x 8-batch dot over 80 depth rows, 8-row weight prefetch ring.
__device__ __forceinline__ void dot80_2(ull a1[4], ull a2[4], const float (*sA)[8],
                                        const float* __restrict__ w1p,
                                        const float* __restrict__ w2p, size_t ws) {
    float b1[8], b2[8];
#pragma unroll
    for (int j = 0; j < 8; j++) { b1[j] = w1p[j * ws]; b2[j] = w2p[j * ws]; }
    const float* f1 = w1p + 8 * ws;
    const float* f2 = w2p + 8 * ws;
#pragma unroll
    for (int g = 0; g < DEP; ++g) {
        float c1 = b1[g & 7], c2 = b2[g & 7];
        if (g < DEP - 8) { b1[g & 7] = *f1; f1 += ws; b2[g & 7] = *f2; f2 += ws; }
        ull W1 = pack2(c1), W2 = pack2(c2);
        const double2* sp = reinterpret_cast<const double2*>(sA[g]);
        double2 q0 = sp[0], q1 = sp[1];
        ull s0 = __double_as_longlong(q0.x);
        ull s1 = __double_as_longlong(q0.y);
        ull s2 = __double_as_longlong(q1.x);
        ull s3 = __double_as_longlong(q1.y);
        ffma2(a1[0], s0, W1); ffma2(a1[1], s1, W1);
        ffma2(a1[2], s2, W1); ffma2(a1[3], s3, W1);
        ffma2(a2[0], s0, W2); ffma2(a2[1], s1, W2);
        ffma2(a2[2], s2, W2); ffma2(a2[3], s3, W2);
    }
}

__device__ __forceinline__ void fill_T8(float (*dst)[8], const float* __restrict__ srcT,
                                        int bg, int hbase) {
    for (int idx = threadIdx.x; idx < DEP * 8; idx += NTHR) {
        int hh = idx >> 3, bb = idx & 7;
        dst[hh][bb] = srcT[(hbase + hh) * kB + bg * 8 + bb];
    }
}

// ---- A tile: jointT @ Wc -> d_part ----
__device__ void A_tile(int tt, float (*sA)[8], const float* __restrict__ Wc) {
    int hs = tt & 7, vch = (tt >> 3) % 10, bg = tt / 80;
    int hbase = hs * DEP;
    fill_T8(sA, d_jointT, bg, hbase);
    __syncthreads();
    int tid = threadIdx.x;
    int v1 = vch * 512 + tid;
    int v2 = v1 + 256;
    bool ok2 = v2 < kV;
    const float* w1 = Wc + (size_t)hbase * kV + v1;
    const float* w2 = Wc + (size_t)hbase * kV + (ok2 ? v2 : v1);
    ull a1[4] = {0, 0, 0, 0}, a2[4] = {0, 0, 0, 0};
    dot80_2(a1, a2, sA, w1, w2, kV);
    size_t rb = (size_t)(hs * kB + bg * 8) * kV;
#pragma unroll
    for (int i = 0; i < 4; i++) {
        float2 f = unpack2(a1[i]);
        d_part[rb + (size_t)(2 * i) * kV + v1] = f.x;
        d_part[rb + (size_t)(2 * i + 1) * kV + v1] = f.y;
    }
    if (ok2) {
#pragma unroll
        for (int i = 0; i < 4; i++) {
            float2 f = unpack2(a2[i]);
            d_part[rb + (size_t)(2 * i) * kV + v2] = f.x;
            d_part[rb + (size_t)(2 * i + 1) * kV + v2] = f.y;
        }
    }
}

// ---- CH tile: hT @ Wh -> d_gpart ----
__device__ void CH_tile(int u, float (*sA)[8], const float* __restrict__ Wh) {
    int hs = u & 7, jch = (u >> 3) % 5, bg = u / 40;
    int hbase = hs * DEP;
    fill_T8(sA, d_hT, bg, hbase);
    __syncthreads();
    int tid = threadIdx.x;
    int j1 = jch * 512 + tid;
    int j2 = j1 + 256;
    const float* w1 = Wh + (size_t)hbase * kG + j1;
    const float* w2 = Wh + (size_t)hbase * kG + j2;
    ull a1[4] = {0, 0, 0, 0}, a2[4] = {0, 0, 0, 0};
    dot80_2(a1, a2, sA, w1, w2, kG);
    int g1 = j1 / kH, k1 = j1 - g1 * kH;
    int g2 = j2 / kH, k2 = j2 - g2 * kH;
#pragma unroll
    for (int i = 0; i < 4; i++) {
        float2 f = unpack2(a1[i]);
        d_gpart[(((size_t)hs * kB + bg * 8 + 2 * i) * kH + k1) * 4 + g1] = f.x;
        d_gpart[(((size_t)hs * kB + bg * 8 + 2 * i + 1) * kH + k1) * 4 + g1] = f.y;
    }
#pragma unroll
    for (int i = 0; i < 4; i++) {
        float2 f = unpack2(a2[i]);
        d_gpart[(((size_t)hs * kB + bg * 8 + 2 * i) * kH + k2) * 4 + g2] = f.x;
        d_gpart[(((size_t)hs * kB + bg * 8 + 2 * i + 1) * kH + k2) * 4 + g2] = f.y;
    }
}

// ---- fused phase: B partial + flag-sync + cooperative C2 (block ch owns k-range) ----
__device__ void phaseBC(int t, const float* __restrict__ bc, const float* __restrict__ tn,
                        const float* __restrict__ bias, float* __restrict__ out,
                        float* s_f, int* s_i, float* s_s) {
    int u = blockIdx.x;            // < 256
    int b = u >> 3, ch = u & 7;
    int p = t & 1;
    int v0 = ch * 640;
    int tid = threadIdx.x;

    // -- B partial: argmax + sumexp over this chunk --
    float m = -1e30f; int mi = 0x7fffffff; float se = 0.f;
    int v = v0 + 4 * tid;
    if (tid < 160 && v < kV) {
        float4 s = *(const float4*)&bc[v];
#pragma unroll
        for (int hs = 0; hs < HS; hs++) {
            float4 pp = *(const float4*)&d_part[((size_t)(hs * kB + b)) * kV + v];
            s.x += pp.x; s.y += pp.y; s.z += pp.z; s.w += pp.w;
        }
        se = expf(s.x) + expf(s.y) + expf(s.z) + expf(s.w);
        m = s.x; mi = v;
        if (s.y > m) { m = s.y; mi = v + 1; }
        if (s.z > m) { m = s.z; mi = v + 2; }
        if (s.w > m) { m = s.w; mi = v + 3; }
    }
    s_f[tid] = m; s_i[tid] = mi; s_s[tid] = se;
    __syncthreads();
    for (int w = 128; w; w >>= 1) {
        if (tid < w) {
            float om = s_f[tid + w]; int oi = s_i[tid + w];
            if (om > s_f[tid] || (om == s_f[tid] && oi < s_i[tid])) { s_f[tid] = om; s_i[tid] = oi; }
            s_s[tid] += s_s[tid + w];
        }
        __syncthreads();
    }
    if (tid == 0) {
        d_bmax[u] = s_f[0]; d_bidx[u] = s_i[0]; d_bsum[u] = s_s[0];
        d_bcnt[p ^ 1][b] = 0;          // reset other parity (consumed last step; barrier-safe)
        __threadfence();
        atomicAdd(&d_bcnt[p][b], 1);
        while (ld_cg_i(&d_bcnt[p][b]) < BCH) { __nanosleep(20); }
    }
    __syncthreads();

    // -- all 8 blocks of batch b proceed: combine partials (redundantly) --
    float M = -1e30f; int MI = 0; float S = 0.f;
#pragma unroll
    for (int c = 0; c < BCH; c++) {
        float cm = __ldcg(&d_bmax[b * BCH + c]);
        int ci = __ldcg(&d_bidx[b * BCH + c]);
        S += __ldcg(&d_bsum[b * BCH + c]);
        if (cm > M) { M = cm; MI = ci; }
    }
    int upd = (MI != 0);
    int nt = upd ? MI : ld_cg_i(&d_tok[b]);

    // -- cooperative C2: this block owns k in [ch*80, ch*80+80) --
    if (t < kT - 1 && tid < DEP) {
        int k = ch * DEP + tid;
        float hnew;
        if (upd) {
            float4 a = *(const float4*)&d_xwx[((size_t)nt * kH + k) * 4];
            a.x += bias[k]; a.y += bias[kH + k];
            a.z += bias[2 * kH + k]; a.w += bias[3 * kH + k];
#pragma unroll
            for (int hs = 0; hs < HS; hs++) {
                float4 pp = *(const float4*)&d_gpart[(((size_t)hs * kB + b) * kH + k) * 4];
                a.x += pp.x; a.y += pp.y; a.z += pp.z; a.w += pp.w;
            }
            float cold = d_c[b * kH + k];          // owned by this block across steps
            float c2v = sigf(a.y) * cold + sigf(a.x) * tanhf(a.z);
            float h2 = sigf(a.w) * tanhf(c2v);
            d_c[b * kH + k] = c2v;
            d_hT[k * kB + b] = h2;
            hnew = h2;
        } else {
            hnew = d_hT[k * kB + b];
        }
        d_jointT[k * kB + b] = tanhf(tn[((size_t)b * kT + (t + 1)) * kH + k] + hnew);
    }

    if (ch == 0 && tid == 0) {
        float val = M - logf(S);
        float sc = d_scores[b] + (upd ? val : 0.f);
        d_scores[b] = sc;
        if (t == kT - 1) out[b] = sc;
        out[kB + (size_t)b * kT + t] = (float)(upd ? MI : 0);
        if (upd) d_tok[b] = MI;
    }
}

// ---- one-time: xWx = embed @ Wx -> [v][k][gate] ----
__device__ void precompute_xwx(const float* __restrict__ embed, const float* __restrict__ Wx,
                               float (*sA)[8]) {
    for (int tp = blockIdx.x; tp < PT; tp += NBLK) {
        int rb = tp / 5, jch = tp % 5;
        int v0 = rb * 8;
        int tid = threadIdx.x;
        int j1 = jch * 512 + tid, j2 = j1 + 256;
        ull a1[4] = {0, 0, 0, 0}, a2[4] = {0, 0, 0, 0};
        for (int hs = 0; hs < HS; hs++) {
            __syncthreads();
            for (int idx = tid; idx < DEP * 8; idx += NTHR) {
                int hh = idx >> 3, bb = idx & 7;
                sA[hh][bb] = embed[(size_t)(v0 + bb) * kH + hs * DEP + hh];
            }
            __syncthreads();
            dot80_2(a1, a2, sA, Wx + (size_t)(hs * DEP) * kG + j1,
                    Wx + (size_t)(hs * DEP) * kG + j2, kG);
        }
        int g1 = j1 / kH, k1 = j1 - g1 * kH;
        int g2 = j2 / kH, k2 = j2 - g2 * kH;
#pragma unroll
        for (int i = 0; i < 4; i++) {
            float2 f1 = unpack2(a1[i]);
            float2 f2 = unpack2(a2[i]);
            d_xwx[((size_t)(v0 + 2 * i) * kH + k1) * 4 + g1] = f1.x;
            d_xwx[((size_t)(v0 + 2 * i + 1) * kH + k1) * 4 + g1] = f1.y;
            d_xwx[((size_t)(v0 + 2 * i) * kH + k2) * 4 + g2] = f2.x;
            d_xwx[((size_t)(v0 + 2 * i + 1) * kH + k2) * 4 + g2] = f2.y;
        }
        __syncthreads();
    }
}

__device__ void initC2(const float* __restrict__ tn, const float* __restrict__ bias) {
    int gid = blockIdx.x * NTHR + threadIdx.x;
    if (gid >= kB * kH) return;
    int b = gid / kH, k = gid - b * kH;
    float4 a = *(const float4*)&d_xwx[(size_t)k * 4];
    a.x += bias[k]; a.y += bias[kH + k]; a.z += bias[2 * kH + k]; a.w += bias[3 * kH + k];
    float c1 = sigf(a.x) * tanhf(a.z);
    float h1 = sigf(a.w) * tanhf(c1);
    d_c[gid] = c1;
    d_hT[k * kB + b] = h1;
    d_jointT[k * kB + b] = tanhf(tn[(size_t)b * kT * kH + k] + h1);
    if (k == 0) { d_scores[b] = 0.f; d_tok[b] = 0; d_bcnt[0][b] = 0; d_bcnt[1][b] = 0; }
}

__global__ void __launch_bounds__(NTHR, 4)
transducer_kernel(const float* __restrict__ tn, const float* __restrict__ embed,
                  const float* __restrict__ Wx, const float* __restrict__ Wh,
                  const float* __restrict__ bias, const float* __restrict__ Wc,
                  const float* __restrict__ bc, float* __restrict__ out) {
    __shared__ __align__(16) float sA[DEP][8];
    __shared__ float s_f[NTHR];
    __shared__ int   s_i[NTHR];
    __shared__ float s_s[NTHR];

    precompute_xwx(embed, Wx, sA);
    grid_barrier();
    initC2(tn, bias);
    grid_barrier();

    for (int t = 0; t < kT; ++t) {
        // phase 1: A (joint@Wc) and CH (h@Wh) in parallel, static mapping
        if (blockIdx.x < TILES_A) {
            A_tile(blockIdx.x, sA, Wc);
        } else if (t < kT - 1 && blockIdx.x < TILES_A + TILES_CH) {
            CH_tile(blockIdx.x - TILES_A, sA, Wh);
        }
        grid_barrier();

        // phase 2: fused B -> cooperative C2 (blocks 0..255)
        if (blockIdx.x < kB * BCH) {
            phaseBC(t, bc, tn, bias, out, s_f, s_i, s_s);
        }
        grid_barrier();
    }
}

extern "C" void kernel_launch(void* const* d_in, const int* in_sizes, int n_in,
                              void* d_out, int out_size) {
    const float* tn    = (const float*)d_in[0];
    const float* embed = (const float*)d_in[1];
    const float* Wx    = (const float*)d_in[2];
    const float* Wh    = (const float*)d_in[3];
    const float* bias  = (const float*)d_in[4];
    const float* Wc    = (const float*)d_in[5];
    const float* bc    = (const float*)d_in[6];
    float* out = (float*)d_out;
    (void)in_sizes; (void)n_in; (void)out_size;
    transducer_kernel<<<NBLK, NTHR>>>(tn, embed, Wx, Wh, bias, Wc, bc, out);
}